// round 2
// baseline (speedup 1.0000x reference)
#include <cuda_runtime.h>
#include <cuda_bf16.h>
#include <cstdint>

// ---------------- problem constants ----------------
#define BB 4
#define HH 128
#define HID 7168
#define QL 1536
#define KVL 512
#define DN 128
#define DR 64
#define DV 128
#define DQK 192
#define TT 1025          // PAST + 1
#define QROWS (HH*DQK)   // 24576
#define CTXD (HH*DV)     // 16384
#define QFD 576          // KVL + DR
// 1/sqrt(192)
#define SCALE_QK 0.07216878364870323f

// ---------------- device scratch (no allocations allowed) ----------------
__device__ float g_qa[BB*QL];
__device__ float g_qan[BB*QL];
__device__ float g_q[BB*QROWS];
__device__ float g_ckv[BB*QFD];
__device__ float g_qfull[BB*HH*QFD];    // absorbed q_lat | q_pe, pre-scaled
__device__ float g_ctxlat[BB*HH*KVL];
__device__ float g_ctx[BB*CTXD];
__device__ float g_ct[BB*QFD*TT];       // transposed cache [b][k][t]

// position_ids may be int32 (JAX x64 disabled) or int64. Decode robustly:
// int64 little-endian values < 2^31 have zero odd words.
__device__ __forceinline__ int get_pos(const int* __restrict__ p, int b)
{
    bool is64 = (p[1] == 0) && (p[3] == 0) && (p[0] != 0);
    return is64 ? p[2*b] : p[b];
}

// ---------------- generic GEMV: out[b][row] = A[row,:] . X[b,:], 4 batches fused ----------------
__global__ void gemv4_kernel(const float4* __restrict__ A, const float4* __restrict__ X,
                             float* __restrict__ out, int K4, int rows)
{
    int row = blockIdx.x;
    int tid = threadIdx.x;
    const float4* a = A + (size_t)row * K4;
    float a0 = 0.f, a1 = 0.f, a2 = 0.f, a3 = 0.f;
    for (int i = tid; i < K4; i += 128) {
        float4 av = a[i];
        float4 x0 = X[i];
        float4 x1 = X[(size_t)K4 + i];
        float4 x2 = X[(size_t)2*K4 + i];
        float4 x3 = X[(size_t)3*K4 + i];
        a0 += av.x*x0.x + av.y*x0.y + av.z*x0.z + av.w*x0.w;
        a1 += av.x*x1.x + av.y*x1.y + av.z*x1.z + av.w*x1.w;
        a2 += av.x*x2.x + av.y*x2.y + av.z*x2.z + av.w*x2.w;
        a3 += av.x*x3.x + av.y*x3.y + av.z*x3.z + av.w*x3.w;
    }
    #pragma unroll
    for (int off = 16; off; off >>= 1) {
        a0 += __shfl_xor_sync(0xffffffffu, a0, off);
        a1 += __shfl_xor_sync(0xffffffffu, a1, off);
        a2 += __shfl_xor_sync(0xffffffffu, a2, off);
        a3 += __shfl_xor_sync(0xffffffffu, a3, off);
    }
    __shared__ float red[4][4];
    int w = tid >> 5;
    if ((tid & 31) == 0) { red[0][w]=a0; red[1][w]=a1; red[2][w]=a2; red[3][w]=a3; }
    __syncthreads();
    if (tid < 4) {
        float s = red[tid][0] + red[tid][1] + red[tid][2] + red[tid][3];
        out[(size_t)tid * rows + row] = s;
    }
}

// ---------------- w_o GEMV: activations staged via smem (256KB > L1) ----------------
#define WOK 16384
#define WOKT 2048   // floats per tile (per batch)
__global__ void gemv_wo_kernel(const float4* __restrict__ A, const float4* __restrict__ X,
                               float* __restrict__ out)
{
    __shared__ float4 sx[4][WOKT/4];   // 32 KB
    int tid = threadIdx.x, w = tid >> 5, lane = tid & 31;
    int row = blockIdx.x * 8 + w;
    const float4* arow = A + (size_t)row * (WOK/4);
    float acc[4] = {0.f, 0.f, 0.f, 0.f};
    for (int kt = 0; kt < WOK; kt += WOKT) {
        __syncthreads();
        for (int i = tid; i < 4*(WOKT/4); i += 256) {
            int b = i / (WOKT/4), j = i % (WOKT/4);
            sx[b][j] = X[(size_t)b*(WOK/4) + (kt/4) + j];
        }
        __syncthreads();
        for (int i = lane; i < WOKT/4; i += 32) {
            float4 av = arow[kt/4 + i];
            #pragma unroll
            for (int b = 0; b < 4; b++) {
                float4 xv = sx[b][i];
                acc[b] += av.x*xv.x + av.y*xv.y + av.z*xv.z + av.w*xv.w;
            }
        }
    }
    #pragma unroll
    for (int b = 0; b < 4; b++)
        #pragma unroll
        for (int off = 16; off; off >>= 1)
            acc[b] += __shfl_xor_sync(0xffffffffu, acc[b], off);
    if (lane == 0) {
        #pragma unroll
        for (int b = 0; b < 4; b++) out[(size_t)b*HID + row] = acc[b];
    }
}

// ---------------- rmsnorm of q_a ----------------
__global__ void rmsnorm_q_kernel(const float* __restrict__ gamma)
{
    int b = blockIdx.x, tid = threadIdx.x;
    float ss = 0.f;
    for (int i = tid; i < QL; i += 256) { float v = g_qa[b*QL+i]; ss += v*v; }
    #pragma unroll
    for (int off = 16; off; off >>= 1) ss += __shfl_xor_sync(0xffffffffu, ss, off);
    __shared__ float r[8];
    __shared__ float s_rs;
    if ((tid & 31) == 0) r[tid >> 5] = ss;
    __syncthreads();
    if (tid == 0) {
        float t = 0.f;
        #pragma unroll
        for (int i = 0; i < 8; i++) t += r[i];
        s_rs = rsqrtf(t / (float)QL + 1e-6f);
    }
    __syncthreads();
    for (int i = tid; i < QL; i += 256) g_qan[b*QL+i] = g_qa[b*QL+i] * s_rs * gamma[i];
}

// ---------------- RoPE on q_pe (in place) ----------------
__global__ void rope_q_kernel(const float* __restrict__ cosT, const float* __restrict__ sinT,
                              const int* __restrict__ posw)
{
    int h = blockIdx.x, b = blockIdx.y, d = threadIdx.x;   // 64 threads
    float* qp = g_q + (size_t)b*QROWS + h*DQK + DN;
    float v  = qp[d];
    float pr = (d < 32) ? -qp[d+32] : qp[d-32];
    int p = get_pos(posw, b);
    float res = v * cosT[(size_t)p*DR + d] + pr * sinT[(size_t)p*DR + d];
    __syncthreads();
    qp[d] = res;
}

// ---------------- ckv postprocess: rmsnorm + k_pe RoPE -> new cache row ----------------
__global__ void ckv_post_kernel(const float* __restrict__ gkv, const float* __restrict__ cosT,
                                const float* __restrict__ sinT, const int* __restrict__ posw,
                                float* __restrict__ out_cache)
{
    int b = blockIdx.x, tid = threadIdx.x;
    const float* cv = g_ckv + b*QFD;
    float ss = 0.f;
    for (int i = tid; i < KVL; i += 256) { float v = cv[i]; ss += v*v; }
    #pragma unroll
    for (int off = 16; off; off >>= 1) ss += __shfl_xor_sync(0xffffffffu, ss, off);
    __shared__ float r[8];
    __shared__ float s_rs;
    if ((tid & 31) == 0) r[tid >> 5] = ss;
    __syncthreads();
    if (tid == 0) {
        float t = 0.f;
        #pragma unroll
        for (int i = 0; i < 8; i++) t += r[i];
        s_rs = rsqrtf(t / (float)KVL + 1e-6f);
    }
    __syncthreads();
    float* dst = out_cache + ((size_t)b*TT + (TT-1)) * QFD;
    for (int i = tid; i < KVL; i += 256) dst[i] = cv[i] * s_rs * gkv[i];
    if (tid < DR) {
        int d = tid;
        int p = get_pos(posw, b);
        float v  = cv[KVL + d];
        float pr = (d < 32) ? -cv[KVL + d + 32] : cv[KVL + d - 32];
        dst[KVL + d] = v * cosT[(size_t)p*DR + d] + pr * sinT[(size_t)p*DR + d];
    }
}

// ---------------- copy past cache rows into output cache ----------------
__global__ void copy_cache_kernel(const float4* __restrict__ past, float* __restrict__ out_cache)
{
    int t = blockIdx.x, b = blockIdx.y, i = threadIdx.x;   // 144 threads (576/4)
    float4* dst = (float4*)(out_cache + ((size_t)b*TT + t) * QFD);
    dst[i] = past[((size_t)b*(TT-1) + t) * (QFD/4) + i];
}

// ---------------- absorption: q_lat[b,h,:] = q_nope[b,h,:] @ W_k[h]; pack q_full ----------------
__global__ void absorb_kernel(const float* __restrict__ w_kvb)
{
    int h = blockIdx.x, c = threadIdx.x;   // 512 threads
    __shared__ float qs[4][DN];
    int b0 = c >> 7, d0 = c & 127;
    qs[b0][d0] = g_q[(size_t)b0*QROWS + h*DQK + d0];
    __syncthreads();
    float acc[4] = {0.f, 0.f, 0.f, 0.f};
    const float* wk = w_kvb + (size_t)h*256*KVL + c;
    #pragma unroll 4
    for (int d = 0; d < DN; d++) {
        float wv = wk[(size_t)d*KVL];
        acc[0] += qs[0][d]*wv; acc[1] += qs[1][d]*wv;
        acc[2] += qs[2][d]*wv; acc[3] += qs[3][d]*wv;
    }
    #pragma unroll
    for (int b = 0; b < 4; b++)
        g_qfull[((size_t)(b*HH + h))*QFD + c] = acc[b] * SCALE_QK;
    if (c < DR) {
        #pragma unroll
        for (int b = 0; b < 4; b++)
            g_qfull[((size_t)(b*HH + h))*QFD + KVL + c] =
                g_q[(size_t)b*QROWS + h*DQK + DN + c] * SCALE_QK;
    }
}

// ---------------- transpose cache -> ct[b][k][t] for coalesced score GEMV ----------------
__global__ void transpose_cache_kernel(const float* __restrict__ cache)
{
    __shared__ float tile[32][33];
    int tb = blockIdx.x * 32, kb = blockIdx.y * 32, b = blockIdx.z;
    int tx = threadIdx.x, ty = threadIdx.y;     // (32, 8)
    for (int i = ty; i < 32; i += 8) {
        int t = tb + i, k = kb + tx;
        if (t < TT && k < QFD) tile[i][tx] = cache[((size_t)b*TT + t)*QFD + k];
    }
    __syncthreads();
    for (int i = ty; i < 32; i += 8) {
        int k = kb + i, t = tb + tx;
        if (t < TT && k < QFD) g_ct[((size_t)b*QFD + k)*TT + t] = tile[tx][i];
    }
}

// ---------------- attention: scores + softmax + ctx_lat (8 heads / block) ----------------
#define SCP TT
__global__ void attn_kernel(const float* __restrict__ cache, const float* __restrict__ mask)
{
    extern __shared__ float sm[];
    float* qsm = sm;               // 8*576
    float* sc  = sm + 8*QFD;       // 8*1025
    __shared__ float s_inv[8];
    int b = blockIdx.y, h0 = blockIdx.x * 8, tid = threadIdx.x;

    for (int i = tid; i < 8*QFD; i += 256) {
        int h = i / QFD, k = i % QFD;
        qsm[i] = g_qfull[((size_t)(b*HH + h0 + h))*QFD + k];
    }
    __syncthreads();

    // ---- phase 1: scores[h][t] = qfull . cache_row(t), t owned per-thread via transposed ct ----
    {
        float acc[8][4];
        #pragma unroll
        for (int h = 0; h < 8; h++)
            #pragma unroll
            for (int rr = 0; rr < 4; rr++) acc[h][rr] = 0.f;
        const float* ctb = g_ct + (size_t)b*QFD*TT;
        for (int k = 0; k < QFD; k++) {
            float qv[8];
            #pragma unroll
            for (int h = 0; h < 8; h++) qv[h] = qsm[h*QFD + k];   // broadcast LDS
            const float* row = ctb + (size_t)k*TT;
            #pragma unroll
            for (int rr = 0; rr < 4; rr++) {
                float cvv = row[tid + 256*rr];
                #pragma unroll
                for (int h = 0; h < 8; h++) acc[h][rr] += qv[h]*cvv;
            }
        }
        #pragma unroll
        for (int rr = 0; rr < 4; rr++) {
            int t = tid + 256*rr;
            float mk = mask[(size_t)b*TT + t];
            #pragma unroll
            for (int h = 0; h < 8; h++) sc[h*SCP + t] = acc[h][rr] + mk;
        }
        if (tid < 32) {   // last row t=1024 by warp 0
            const float* crow = cache + ((size_t)b*TT + (TT-1))*QFD;
            float mk = mask[(size_t)b*TT + (TT-1)];
            for (int h = 0; h < 8; h++) {
                float p = 0.f;
                for (int i = tid; i < QFD; i += 32) p += qsm[h*QFD + i]*crow[i];
                #pragma unroll
                for (int off = 16; off; off >>= 1) p += __shfl_xor_sync(0xffffffffu, p, off);
                if (tid == 0) sc[h*SCP + (TT-1)] = p + mk;
            }
        }
    }
    __syncthreads();

    // ---- phase 2: softmax, warp per head ----
    {
        int w = tid >> 5, lane = tid & 31, h = w;
        float m = -1e30f;
        for (int t = lane; t < TT; t += 32) m = fmaxf(m, sc[h*SCP + t]);
        #pragma unroll
        for (int off = 16; off; off >>= 1) m = fmaxf(m, __shfl_xor_sync(0xffffffffu, m, off));
        float s = 0.f;
        for (int t = lane; t < TT; t += 32) {
            float e = __expf(sc[h*SCP + t] - m);
            sc[h*SCP + t] = e;
            s += e;
        }
        #pragma unroll
        for (int off = 16; off; off >>= 1) s += __shfl_xor_sync(0xffffffffu, s, off);
        if (lane == 0) s_inv[h] = 1.0f / s;
    }
    __syncthreads();

    // ---- phase 3: ctx_lat[h][c] = sum_t attn[h][t] * cache[t][c] ----
    {
        float acc[8][2];
        #pragma unroll
        for (int h = 0; h < 8; h++) { acc[h][0] = 0.f; acc[h][1] = 0.f; }
        const float* cb = cache + (size_t)b*TT*QFD;
        int c0 = tid, c1 = tid + 256;
        for (int t = 0; t < TT; t++) {
            const float* crow = cb + (size_t)t*QFD;
            float v0 = crow[c0], v1 = crow[c1];
            #pragma unroll
            for (int h = 0; h < 8; h++) {
                float a = sc[h*SCP + t];
                acc[h][0] += a*v0; acc[h][1] += a*v1;
            }
        }
        #pragma unroll
        for (int h = 0; h < 8; h++) {
            float inv = s_inv[h];
            size_t base = ((size_t)(b*HH + h0 + h))*KVL;
            g_ctxlat[base + c0] = acc[h][0]*inv;
            g_ctxlat[base + c1] = acc[h][1]*inv;
        }
    }
}

// ---------------- V projection: ctx[b,h,dv] = ctx_lat[b,h,:] . W_v[h][dv,:] ----------------
__global__ void vproj_kernel(const float* __restrict__ w_kvb)
{
    int h = blockIdx.x, tid = threadIdx.x, w = tid >> 5, lane = tid & 31;
    for (int dv = w; dv < DV; dv += 8) {
        const float* wr = w_kvb + ((size_t)(h*256 + DN + dv))*KVL;
        float p0 = 0.f, p1 = 0.f, p2 = 0.f, p3 = 0.f;
        for (int i = lane; i < KVL; i += 32) {
            float wv = wr[i];
            p0 += wv * g_ctxlat[((size_t)(0*HH + h))*KVL + i];
            p1 += wv * g_ctxlat[((size_t)(1*HH + h))*KVL + i];
            p2 += wv * g_ctxlat[((size_t)(2*HH + h))*KVL + i];
            p3 += wv * g_ctxlat[((size_t)(3*HH + h))*KVL + i];
        }
        #pragma unroll
        for (int off = 16; off; off >>= 1) {
            p0 += __shfl_xor_sync(0xffffffffu, p0, off);
            p1 += __shfl_xor_sync(0xffffffffu, p1, off);
            p2 += __shfl_xor_sync(0xffffffffu, p2, off);
            p3 += __shfl_xor_sync(0xffffffffu, p3, off);
        }
        if (lane == 0) {
            g_ctx[(size_t)0*CTXD + h*DV + dv] = p0;
            g_ctx[(size_t)1*CTXD + h*DV + dv] = p1;
            g_ctx[(size_t)2*CTXD + h*DV + dv] = p2;
            g_ctx[(size_t)3*CTXD + h*DV + dv] = p3;
        }
    }
}

// ---------------- host launch ----------------
extern "C" void kernel_launch(void* const* d_in, const int* in_sizes, int n_in,
                              void* d_out, int out_size)
{
    const float* x      = (const float*)d_in[0];
    const float* mask   = (const float*)d_in[1];
    const int*   posw   = (const int*)  d_in[2];   // int32 or int64 (decoded in-kernel)
    const float* past   = (const float*)d_in[3];
    const float* cosT   = (const float*)d_in[4];
    const float* sinT   = (const float*)d_in[5];
    const float* w_qa   = (const float*)d_in[6];
    const float* gq     = (const float*)d_in[7];
    const float* w_qb   = (const float*)d_in[8];
    const float* w_kva  = (const float*)d_in[9];
    const float* gkv    = (const float*)d_in[10];
    const float* w_kvb  = (const float*)d_in[11];
    const float* w_o    = (const float*)d_in[12];

    float* out_attn  = (float*)d_out;                  // [4,1,7168]
    float* out_cache = out_attn + (size_t)BB*HID;      // [4,1025,576]

    float *p_qa, *p_qan, *p_q, *p_ckv, *p_ctx;
    cudaGetSymbolAddress((void**)&p_qa,  g_qa);
    cudaGetSymbolAddress((void**)&p_qan, g_qan);
    cudaGetSymbolAddress((void**)&p_q,   g_q);
    cudaGetSymbolAddress((void**)&p_ckv, g_ckv);
    cudaGetSymbolAddress((void**)&p_ctx, g_ctx);

    // q_a = x @ w_qa.T
    gemv4_kernel<<<QL, 128>>>((const float4*)w_qa, (const float4*)x, p_qa, HID/4, QL);
    // rmsnorm(q_a) * gamma_q
    rmsnorm_q_kernel<<<BB, 256>>>(gq);
    // q = q_an @ w_qb.T
    gemv4_kernel<<<QROWS, 128>>>((const float4*)w_qb, (const float4*)p_qan, p_q, QL/4, QROWS);
    // ckv = x @ w_kva.T
    gemv4_kernel<<<QFD, 128>>>((const float4*)w_kva, (const float4*)x, p_ckv, HID/4, QFD);
    // RoPE q_pe
    rope_q_kernel<<<dim3(HH, BB), DR>>>(cosT, sinT, posw);
    // rmsnorm c_kv + RoPE k_pe -> new cache row (t=1024)
    ckv_post_kernel<<<BB, 256>>>(gkv, cosT, sinT, posw, out_cache);
    // past rows -> output cache
    copy_cache_kernel<<<dim3(TT-1, BB), QFD/4>>>((const float4*)past, out_cache);
    // q absorption (q_nope @ W_k) + pack q_pe, pre-scaled
    absorb_kernel<<<HH, 512>>>(w_kvb);
    // transpose cache for coalesced score pass
    transpose_cache_kernel<<<dim3((TT+31)/32, (QFD+31)/32, BB), dim3(32, 8)>>>(out_cache);
    // attention (scores + softmax + ctx_lat)
    {
        int smem = (8*QFD + 8*SCP) * (int)sizeof(float);
        cudaFuncSetAttribute(attn_kernel, cudaFuncAttributeMaxDynamicSharedMemorySize, smem + 64);
        attn_kernel<<<dim3(HH/8, BB), 256, smem>>>(out_cache, mask);
    }
    // ctx = ctx_lat @ W_v
    vproj_kernel<<<HH, 256>>>(w_kvb);
    // attn_out = ctx @ w_o.T (smem-staged activations)
    gemv_wo_kernel<<<HID/8, 256>>>((const float4*)w_o, (const float4*)p_ctx, out_attn);
}

// round 3
// speedup vs baseline: 1.1660x; 1.1660x over previous
#include <cuda_runtime.h>
#include <cuda_bf16.h>
#include <cstdint>

// ---------------- problem constants ----------------
#define BB 4
#define HH 128
#define HID 7168
#define QL 1536
#define KVL 512
#define DN 128
#define DR 64
#define DV 128
#define DQK 192
#define TT 1025          // PAST + 1
#define QROWS (HH*DQK)   // 24576
#define CTXD (HH*DV)     // 16384
#define QFD 576          // KVL + DR
#define NSPLIT 4
#define SCP2 260
// 1/sqrt(192)
#define SCALE_QK 0.07216878364870323f

// ---------------- device scratch ----------------
__device__ float g_qa[BB*QL];
__device__ float g_qan[BB*QL];
__device__ float g_q[BB*QROWS];
__device__ float g_ckv[BB*QFD];
__device__ float g_qfull[BB*HH*QFD];
__device__ float g_ctxlat[BB*HH*KVL];
__device__ float g_ctx[BB*CTXD];
__device__ float g_ct[BB*QFD*TT];             // transposed cache [b][k][t]
__device__ float g_pm[BB*HH*NSPLIT];          // per-split running max
__device__ float g_ps[BB*HH*NSPLIT];          // per-split exp-sum
__device__ float g_pctx[(size_t)BB*HH*NSPLIT*KVL]; // per-split unnormalized ctx

// position_ids may be int32 or int64
__device__ __forceinline__ int get_pos(const int* __restrict__ p, int b)
{
    bool is64 = (p[1] == 0) && (p[3] == 0) && (p[0] != 0);
    return is64 ? p[2*b] : p[b];
}

// ---------------- GEMV: smem-staged X, NW rows per block (warp per row) ----------------
// out[b][row] = A[row,:] . X[b,:]   for b in 0..3
template<int NW>
__global__ void gemv_smem_kernel(const float4* __restrict__ A, const float4* __restrict__ X,
                                 float* __restrict__ out, int K4, int outStride)
{
    __shared__ float4 sx[4][512];   // 32 KB tile of X
    int tid = threadIdx.x, w = tid >> 5, lane = tid & 31;
    int row = blockIdx.x * NW + w;
    const float4* arow = A + (size_t)row * K4;
    float a0 = 0.f, a1 = 0.f, a2 = 0.f, a3 = 0.f;
    for (int kt = 0; kt < K4; kt += 512) {
        int cur = min(512, K4 - kt);
        __syncthreads();
        #pragma unroll
        for (int b = 0; b < 4; b++)
            for (int i = tid; i < cur; i += NW*32)
                sx[b][i] = X[(size_t)b*K4 + kt + i];
        __syncthreads();
        #pragma unroll 4
        for (int i = lane; i < cur; i += 32) {
            float4 av = arow[kt + i];
            float4 x0 = sx[0][i], x1 = sx[1][i], x2 = sx[2][i], x3 = sx[3][i];
            a0 += av.x*x0.x + av.y*x0.y + av.z*x0.z + av.w*x0.w;
            a1 += av.x*x1.x + av.y*x1.y + av.z*x1.z + av.w*x1.w;
            a2 += av.x*x2.x + av.y*x2.y + av.z*x2.z + av.w*x2.w;
            a3 += av.x*x3.x + av.y*x3.y + av.z*x3.z + av.w*x3.w;
        }
    }
    #pragma unroll
    for (int off = 16; off; off >>= 1) {
        a0 += __shfl_xor_sync(0xffffffffu, a0, off);
        a1 += __shfl_xor_sync(0xffffffffu, a1, off);
        a2 += __shfl_xor_sync(0xffffffffu, a2, off);
        a3 += __shfl_xor_sync(0xffffffffu, a3, off);
    }
    if (lane == 0) {
        out[(size_t)0*outStride + row] = a0;
        out[(size_t)1*outStride + row] = a1;
        out[(size_t)2*outStride + row] = a2;
        out[(size_t)3*outStride + row] = a3;
    }
}

// ---------------- rmsnorm of q_a ----------------
__global__ void rmsnorm_q_kernel(const float* __restrict__ gamma)
{
    int b = blockIdx.x, tid = threadIdx.x;
    float ss = 0.f;
    for (int i = tid; i < QL; i += 256) { float v = g_qa[b*QL+i]; ss += v*v; }
    #pragma unroll
    for (int off = 16; off; off >>= 1) ss += __shfl_xor_sync(0xffffffffu, ss, off);
    __shared__ float r[8];
    __shared__ float s_rs;
    if ((tid & 31) == 0) r[tid >> 5] = ss;
    __syncthreads();
    if (tid == 0) {
        float t = 0.f;
        #pragma unroll
        for (int i = 0; i < 8; i++) t += r[i];
        s_rs = rsqrtf(t / (float)QL + 1e-6f);
    }
    __syncthreads();
    for (int i = tid; i < QL; i += 256) g_qan[b*QL+i] = g_qa[b*QL+i] * s_rs * gamma[i];
}

// ---------------- RoPE on q_pe (in place) ----------------
__global__ void rope_q_kernel(const float* __restrict__ cosT, const float* __restrict__ sinT,
                              const int* __restrict__ posw)
{
    int h = blockIdx.x, b = blockIdx.y, d = threadIdx.x;   // 64 threads
    float* qp = g_q + (size_t)b*QROWS + h*DQK + DN;
    float v  = qp[d];
    float pr = (d < 32) ? -qp[d+32] : qp[d-32];
    int p = get_pos(posw, b);
    float res = v * cosT[(size_t)p*DR + d] + pr * sinT[(size_t)p*DR + d];
    __syncthreads();
    qp[d] = res;
}

// ---------------- ckv postprocess: rmsnorm + k_pe RoPE -> new cache row ----------------
__global__ void ckv_post_kernel(const float* __restrict__ gkv, const float* __restrict__ cosT,
                                const float* __restrict__ sinT, const int* __restrict__ posw,
                                float* __restrict__ out_cache)
{
    int b = blockIdx.x, tid = threadIdx.x;
    const float* cv = g_ckv + b*QFD;
    float ss = 0.f;
    for (int i = tid; i < KVL; i += 256) { float v = cv[i]; ss += v*v; }
    #pragma unroll
    for (int off = 16; off; off >>= 1) ss += __shfl_xor_sync(0xffffffffu, ss, off);
    __shared__ float r[8];
    __shared__ float s_rs;
    if ((tid & 31) == 0) r[tid >> 5] = ss;
    __syncthreads();
    if (tid == 0) {
        float t = 0.f;
        #pragma unroll
        for (int i = 0; i < 8; i++) t += r[i];
        s_rs = rsqrtf(t / (float)KVL + 1e-6f);
    }
    __syncthreads();
    float* dst = out_cache + ((size_t)b*TT + (TT-1)) * QFD;
    for (int i = tid; i < KVL; i += 256) dst[i] = cv[i] * s_rs * gkv[i];
    if (tid < DR) {
        int d = tid;
        int p = get_pos(posw, b);
        float v  = cv[KVL + d];
        float pr = (d < 32) ? -cv[KVL + d + 32] : cv[KVL + d - 32];
        dst[KVL + d] = v * cosT[(size_t)p*DR + d] + pr * sinT[(size_t)p*DR + d];
    }
}

// ---------------- copy past cache rows into output cache ----------------
__global__ void copy_cache_kernel(const float4* __restrict__ past, float* __restrict__ out_cache)
{
    int t = blockIdx.x, b = blockIdx.y, i = threadIdx.x;   // 144 threads
    float4* dst = (float4*)(out_cache + ((size_t)b*TT + t) * QFD);
    dst[i] = past[((size_t)b*(TT-1) + t) * (QFD/4) + i];
}

// ---------------- absorption: q_lat[b,h,:] = q_nope[b,h,:] @ W_k[h]; pack q_full ----------------
__global__ void absorb_kernel(const float* __restrict__ w_kvb)
{
    int h = blockIdx.x, c = threadIdx.x;   // 512 threads
    __shared__ float qs[4][DN];
    int b0 = c >> 7, d0 = c & 127;
    qs[b0][d0] = g_q[(size_t)b0*QROWS + h*DQK + d0];
    __syncthreads();
    float acc[4] = {0.f, 0.f, 0.f, 0.f};
    const float* wk = w_kvb + (size_t)h*256*KVL + c;
    #pragma unroll 4
    for (int d = 0; d < DN; d++) {
        float wv = wk[(size_t)d*KVL];
        acc[0] += qs[0][d]*wv; acc[1] += qs[1][d]*wv;
        acc[2] += qs[2][d]*wv; acc[3] += qs[3][d]*wv;
    }
    #pragma unroll
    for (int b = 0; b < 4; b++)
        g_qfull[((size_t)(b*HH + h))*QFD + c] = acc[b] * SCALE_QK;
    if (c < DR) {
        #pragma unroll
        for (int b = 0; b < 4; b++)
            g_qfull[((size_t)(b*HH + h))*QFD + KVL + c] =
                g_q[(size_t)b*QROWS + h*DQK + DN + c] * SCALE_QK;
    }
}

// ---------------- transpose cache -> ct[b][k][t] ----------------
__global__ void transpose_cache_kernel(const float* __restrict__ cache)
{
    __shared__ float tile[32][33];
    int tb = blockIdx.x * 32, kb = blockIdx.y * 32, b = blockIdx.z;
    int tx = threadIdx.x, ty = threadIdx.y;     // (32, 8)
    for (int i = ty; i < 32; i += 8) {
        int t = tb + i, k = kb + tx;
        if (t < TT && k < QFD) tile[i][tx] = cache[((size_t)b*TT + t)*QFD + k];
    }
    __syncthreads();
    for (int i = ty; i < 32; i += 8) {
        int k = kb + i, t = tb + tx;
        if (t < TT && k < QFD) g_ct[((size_t)b*QFD + k)*TT + t] = tile[tx][i];
    }
}

// ---------------- attention split: scores + partial softmax + partial ctx ----------------
// grid (HH/8, NSPLIT, BB), block 256. split s covers t in [256s, TE) where
// TE = 256(s+1) for s<3, 1025 for s==3 (extra element t=1024 handled by warp 0).
__global__ void attn_split_kernel(const float* __restrict__ cache, const float* __restrict__ mask)
{
    __shared__ float qsm[8*QFD];
    __shared__ float sc[8*SCP2];
    int b = blockIdx.z, split = blockIdx.y, h0 = blockIdx.x * 8, tid = threadIdx.x;
    int T0 = split * 256;
    int TE = (split == NSPLIT-1) ? TT : T0 + 256;
    int cnt = TE - T0;

    for (int i = tid; i < 8*QFD; i += 256) {
        int h = i / QFD, k = i % QFD;
        qsm[i] = g_qfull[((size_t)(b*HH + h0 + h))*QFD + k];
    }
    __syncthreads();

    // ---- phase 1: scores for t = T0 + tid ----
    {
        float acc[8];
        #pragma unroll
        for (int h = 0; h < 8; h++) acc[h] = 0.f;
        const float* ctb = g_ct + (size_t)b*QFD*TT + T0 + tid;
        for (int k = 0; k < QFD; k += 4) {
            float c0 = ctb[(size_t)k*TT];
            float c1 = ctb[(size_t)(k+1)*TT];
            float c2 = ctb[(size_t)(k+2)*TT];
            float c3 = ctb[(size_t)(k+3)*TT];
            #pragma unroll
            for (int h = 0; h < 8; h++) {
                acc[h] += qsm[h*QFD+k]*c0 + qsm[h*QFD+k+1]*c1
                        + qsm[h*QFD+k+2]*c2 + qsm[h*QFD+k+3]*c3;
            }
        }
        float mk = mask[(size_t)b*TT + T0 + tid];
        #pragma unroll
        for (int h = 0; h < 8; h++) sc[h*SCP2 + tid] = acc[h] + mk;

        if (split == NSPLIT-1 && tid < 32) {   // t = 1024 by warp 0
            const float* crow = cache + ((size_t)b*TT + (TT-1))*QFD;
            float mk2 = mask[(size_t)b*TT + (TT-1)];
            for (int h = 0; h < 8; h++) {
                float p = 0.f;
                for (int i = tid; i < QFD; i += 32) p += qsm[h*QFD + i]*crow[i];
                #pragma unroll
                for (int off = 16; off; off >>= 1) p += __shfl_xor_sync(0xffffffffu, p, off);
                if (tid == 0) sc[h*SCP2 + 256] = p + mk2;
            }
        }
    }
    __syncthreads();

    // ---- phase 2: local softmax (warp per head), store m & s ----
    {
        int w = tid >> 5, lane = tid & 31, h = w;
        float m = -1e30f;
        for (int t = lane; t < cnt; t += 32) m = fmaxf(m, sc[h*SCP2 + t]);
        #pragma unroll
        for (int off = 16; off; off >>= 1) m = fmaxf(m, __shfl_xor_sync(0xffffffffu, m, off));
        float s = 0.f;
        for (int t = lane; t < cnt; t += 32) {
            float e = __expf(sc[h*SCP2 + t] - m);
            sc[h*SCP2 + t] = e;
            s += e;
        }
        #pragma unroll
        for (int off = 16; off; off >>= 1) s += __shfl_xor_sync(0xffffffffu, s, off);
        if (lane == 0) {
            int idx = (b*HH + h0 + h)*NSPLIT + split;
            g_pm[idx] = m;
            g_ps[idx] = s;
        }
    }
    __syncthreads();

    // ---- phase 3: partial ctx (unnormalized) ----
    {
        float acc[8][2];
        #pragma unroll
        for (int h = 0; h < 8; h++) { acc[h][0] = 0.f; acc[h][1] = 0.f; }
        const float* cb = cache + (size_t)b*TT*QFD;
        int c0 = tid, c1 = tid + 256;
        for (int t = T0; t < TE; t++) {
            const float* crow = cb + (size_t)t*QFD;
            float v0 = crow[c0], v1 = crow[c1];
            int tl = t - T0;
            #pragma unroll
            for (int h = 0; h < 8; h++) {
                float a = sc[h*SCP2 + tl];
                acc[h][0] += a*v0; acc[h][1] += a*v1;
            }
        }
        #pragma unroll
        for (int h = 0; h < 8; h++) {
            size_t base = ((size_t)(b*HH + h0 + h)*NSPLIT + split)*KVL;
            g_pctx[base + c0] = acc[h][0];
            g_pctx[base + c1] = acc[h][1];
        }
    }
}

// ---------------- flash combine over splits ----------------
__global__ void attn_combine_kernel()
{
    int h = blockIdx.x, b = blockIdx.y, tid = threadIdx.x;
    int idx = b*HH + h;
    float m = -1e30f;
    #pragma unroll
    for (int s = 0; s < NSPLIT; s++) m = fmaxf(m, g_pm[idx*NSPLIT + s]);
    float e[NSPLIT]; float ssum = 0.f;
    #pragma unroll
    for (int s = 0; s < NSPLIT; s++) {
        e[s] = __expf(g_pm[idx*NSPLIT + s] - m);
        ssum += g_ps[idx*NSPLIT + s] * e[s];
    }
    float inv = 1.0f / ssum;
    for (int c = tid; c < KVL; c += 256) {
        float acc = 0.f;
        #pragma unroll
        for (int s = 0; s < NSPLIT; s++)
            acc += g_pctx[((size_t)idx*NSPLIT + s)*KVL + c] * e[s];
        g_ctxlat[(size_t)idx*KVL + c] = acc * inv;
    }
}

// ---------------- V projection ----------------
__global__ void vproj_kernel(const float* __restrict__ w_kvb)
{
    int h = blockIdx.x, tid = threadIdx.x, w = tid >> 5, lane = tid & 31;
    for (int dv = w; dv < DV; dv += 8) {
        const float* wr = w_kvb + ((size_t)(h*256 + DN + dv))*KVL;
        float p0 = 0.f, p1 = 0.f, p2 = 0.f, p3 = 0.f;
        #pragma unroll 4
        for (int i = lane; i < KVL; i += 32) {
            float wv = wr[i];
            p0 += wv * g_ctxlat[((size_t)(0*HH + h))*KVL + i];
            p1 += wv * g_ctxlat[((size_t)(1*HH + h))*KVL + i];
            p2 += wv * g_ctxlat[((size_t)(2*HH + h))*KVL + i];
            p3 += wv * g_ctxlat[((size_t)(3*HH + h))*KVL + i];
        }
        #pragma unroll
        for (int off = 16; off; off >>= 1) {
            p0 += __shfl_xor_sync(0xffffffffu, p0, off);
            p1 += __shfl_xor_sync(0xffffffffu, p1, off);
            p2 += __shfl_xor_sync(0xffffffffu, p2, off);
            p3 += __shfl_xor_sync(0xffffffffu, p3, off);
        }
        if (lane == 0) {
            g_ctx[(size_t)0*CTXD + h*DV + dv] = p0;
            g_ctx[(size_t)1*CTXD + h*DV + dv] = p1;
            g_ctx[(size_t)2*CTXD + h*DV + dv] = p2;
            g_ctx[(size_t)3*CTXD + h*DV + dv] = p3;
        }
    }
}

// ---------------- host launch ----------------
extern "C" void kernel_launch(void* const* d_in, const int* in_sizes, int n_in,
                              void* d_out, int out_size)
{
    const float* x      = (const float*)d_in[0];
    const float* mask   = (const float*)d_in[1];
    const int*   posw   = (const int*)  d_in[2];
    const float* past   = (const float*)d_in[3];
    const float* cosT   = (const float*)d_in[4];
    const float* sinT   = (const float*)d_in[5];
    const float* w_qa   = (const float*)d_in[6];
    const float* gq     = (const float*)d_in[7];
    const float* w_qb   = (const float*)d_in[8];
    const float* w_kva  = (const float*)d_in[9];
    const float* gkv    = (const float*)d_in[10];
    const float* w_kvb  = (const float*)d_in[11];
    const float* w_o    = (const float*)d_in[12];

    float* out_attn  = (float*)d_out;                  // [4,1,7168]
    float* out_cache = out_attn + (size_t)BB*HID;      // [4,1025,576]

    float *p_qa, *p_qan, *p_q, *p_ckv, *p_ctx;
    cudaGetSymbolAddress((void**)&p_qa,  g_qa);
    cudaGetSymbolAddress((void**)&p_qan, g_qan);
    cudaGetSymbolAddress((void**)&p_q,   g_q);
    cudaGetSymbolAddress((void**)&p_ckv, g_ckv);
    cudaGetSymbolAddress((void**)&p_ctx, g_ctx);

    // q_a = x @ w_qa.T         (44 MB weight stream)
    gemv_smem_kernel<8><<<QL/8, 256>>>((const float4*)w_qa, (const float4*)x, p_qa, HID/4, QL);
    // ckv = x @ w_kva.T        (16.5 MB)
    gemv_smem_kernel<8><<<QFD/8, 256>>>((const float4*)w_kva, (const float4*)x, p_ckv, HID/4, QFD);
    // rmsnorm(q_a)
    rmsnorm_q_kernel<<<BB, 256>>>(gq);
    // q = q_an @ w_qb.T        (151 MB)
    gemv_smem_kernel<16><<<QROWS/16, 512>>>((const float4*)w_qb, (const float4*)p_qan, p_q, QL/4, QROWS);
    // rmsnorm c_kv + RoPE k_pe -> cache row t=1024
    ckv_post_kernel<<<BB, 256>>>(gkv, cosT, sinT, posw, out_cache);
    // past rows -> output cache
    copy_cache_kernel<<<dim3(TT-1, BB), QFD/4>>>((const float4*)past, out_cache);
    // RoPE q_pe
    rope_q_kernel<<<dim3(HH, BB), DR>>>(cosT, sinT, posw);
    // absorption + q packing
    absorb_kernel<<<HH, 512>>>(w_kvb);
    // transpose cache
    transpose_cache_kernel<<<dim3((TT+31)/32, (QFD+31)/32, BB), dim3(32, 8)>>>(out_cache);
    // attention: split-KV
    attn_split_kernel<<<dim3(HH/8, NSPLIT, BB), 256>>>(out_cache, mask);
    attn_combine_kernel<<<dim3(HH, BB), 256>>>();
    // ctx = ctx_lat @ W_v      (33 MB)
    vproj_kernel<<<HH, 256>>>(w_kvb);
    // attn_out = ctx @ w_o.T   (470 MB)
    gemv_smem_kernel<16><<<HID/16, 512>>>((const float4*)w_o, (const float4*)p_ctx, out_attn, CTXD/4, HID);
}

// round 4
// speedup vs baseline: 1.1728x; 1.0058x over previous
#include <cuda_runtime.h>
#include <cuda_bf16.h>
#include <cstdint>

// ---------------- problem constants ----------------
#define BB 4
#define HH 128
#define HID 7168
#define QL 1536
#define KVL 512
#define DN 128
#define DR 64
#define DV 128
#define DQK 192
#define TT 1025          // PAST + 1
#define QROWS (HH*DQK)   // 24576
#define CTXD (HH*DV)     // 16384
#define QFD 576          // KVL + DR
#define NSPLIT 4
#define SCP2 260
// 1/sqrt(192)
#define SCALE_QK 0.07216878364870323f

// ---------------- device scratch ----------------
__device__ float g_qa[BB*QL];
__device__ float g_qan[BB*QL];
__device__ float g_q[BB*QROWS];
__device__ float g_ckv[BB*QFD];
__device__ float g_qfull[BB*HH*QFD];
__device__ float g_ctxlat[BB*HH*KVL];
__device__ float g_ctx[BB*CTXD];
__device__ float g_ct[BB*QFD*TT];             // transposed cache [b][k][t]
__device__ float g_pm[BB*HH*NSPLIT];          // per-split running max
__device__ float g_ps[BB*HH*NSPLIT];          // per-split exp-sum
__device__ float g_pctx[(size_t)BB*HH*NSPLIT*KVL]; // per-split unnormalized ctx

// position_ids may be int32 or int64
__device__ __forceinline__ int get_pos(const int* __restrict__ p, int b)
{
    bool is64 = (p[1] == 0) && (p[3] == 0) && (p[0] != 0);
    return is64 ? p[2*b] : p[b];
}

// ---------------- GEMV: smem-staged X, NW rows per block (warp per row) ----------------
// out[b][row] = A[row,:] . X[b,:]   for b in 0..3
template<int NW>
__global__ void gemv_smem_kernel(const float4* __restrict__ A, const float4* __restrict__ X,
                                 float* __restrict__ out, int K4, int outStride)
{
    __shared__ float4 sx[4][512];   // 32 KB tile of X
    int tid = threadIdx.x, w = tid >> 5, lane = tid & 31;
    int row = blockIdx.x * NW + w;
    const float4* arow = A + (size_t)row * K4;
    float a0 = 0.f, a1 = 0.f, a2 = 0.f, a3 = 0.f;
    for (int kt = 0; kt < K4; kt += 512) {
        int cur = min(512, K4 - kt);
        __syncthreads();
        #pragma unroll
        for (int b = 0; b < 4; b++)
            for (int i = tid; i < cur; i += NW*32)
                sx[b][i] = X[(size_t)b*K4 + kt + i];
        __syncthreads();
        #pragma unroll 4
        for (int i = lane; i < cur; i += 32) {
            float4 av = arow[kt + i];
            float4 x0 = sx[0][i], x1 = sx[1][i], x2 = sx[2][i], x3 = sx[3][i];
            a0 += av.x*x0.x + av.y*x0.y + av.z*x0.z + av.w*x0.w;
            a1 += av.x*x1.x + av.y*x1.y + av.z*x1.z + av.w*x1.w;
            a2 += av.x*x2.x + av.y*x2.y + av.z*x2.z + av.w*x2.w;
            a3 += av.x*x3.x + av.y*x3.y + av.z*x3.z + av.w*x3.w;
        }
    }
    #pragma unroll
    for (int off = 16; off; off >>= 1) {
        a0 += __shfl_xor_sync(0xffffffffu, a0, off);
        a1 += __shfl_xor_sync(0xffffffffu, a1, off);
        a2 += __shfl_xor_sync(0xffffffffu, a2, off);
        a3 += __shfl_xor_sync(0xffffffffu, a3, off);
    }
    if (lane == 0) {
        out[(size_t)0*outStride + row] = a0;
        out[(size_t)1*outStride + row] = a1;
        out[(size_t)2*outStride + row] = a2;
        out[(size_t)3*outStride + row] = a3;
    }
}

// ---------------- rmsnorm of q_a ----------------
__global__ void rmsnorm_q_kernel(const float* __restrict__ gamma)
{
    int b = blockIdx.x, tid = threadIdx.x;
    float ss = 0.f;
    for (int i = tid; i < QL; i += 256) { float v = g_qa[b*QL+i]; ss += v*v; }
    #pragma unroll
    for (int off = 16; off; off >>= 1) ss += __shfl_xor_sync(0xffffffffu, ss, off);
    __shared__ float r[8];
    __shared__ float s_rs;
    if ((tid & 31) == 0) r[tid >> 5] = ss;
    __syncthreads();
    if (tid == 0) {
        float t = 0.f;
        #pragma unroll
        for (int i = 0; i < 8; i++) t += r[i];
        s_rs = rsqrtf(t / (float)QL + 1e-6f);
    }
    __syncthreads();
    for (int i = tid; i < QL; i += 256) g_qan[b*QL+i] = g_qa[b*QL+i] * s_rs * gamma[i];
}

// ---------------- RoPE on q_pe (in place) ----------------
__global__ void rope_q_kernel(const float* __restrict__ cosT, const float* __restrict__ sinT,
                              const int* __restrict__ posw)
{
    int h = blockIdx.x, b = blockIdx.y, d = threadIdx.x;   // 64 threads
    float* qp = g_q + (size_t)b*QROWS + h*DQK + DN;
    float v  = qp[d];
    float pr = (d < 32) ? -qp[d+32] : qp[d-32];
    int p = get_pos(posw, b);
    float res = v * cosT[(size_t)p*DR + d] + pr * sinT[(size_t)p*DR + d];
    __syncthreads();
    qp[d] = res;
}

// ---------------- ckv postprocess: rmsnorm + k_pe RoPE -> new cache row ----------------
__global__ void ckv_post_kernel(const float* __restrict__ gkv, const float* __restrict__ cosT,
                                const float* __restrict__ sinT, const int* __restrict__ posw,
                                float* __restrict__ out_cache)
{
    int b = blockIdx.x, tid = threadIdx.x;
    const float* cv = g_ckv + b*QFD;
    float ss = 0.f;
    for (int i = tid; i < KVL; i += 256) { float v = cv[i]; ss += v*v; }
    #pragma unroll
    for (int off = 16; off; off >>= 1) ss += __shfl_xor_sync(0xffffffffu, ss, off);
    __shared__ float r[8];
    __shared__ float s_rs;
    if ((tid & 31) == 0) r[tid >> 5] = ss;
    __syncthreads();
    if (tid == 0) {
        float t = 0.f;
        #pragma unroll
        for (int i = 0; i < 8; i++) t += r[i];
        s_rs = rsqrtf(t / (float)KVL + 1e-6f);
    }
    __syncthreads();
    float* dst = out_cache + ((size_t)b*TT + (TT-1)) * QFD;
    for (int i = tid; i < KVL; i += 256) dst[i] = cv[i] * s_rs * gkv[i];
    if (tid < DR) {
        int d = tid;
        int p = get_pos(posw, b);
        float v  = cv[KVL + d];
        float pr = (d < 32) ? -cv[KVL + d + 32] : cv[KVL + d - 32];
        dst[KVL + d] = v * cosT[(size_t)p*DR + d] + pr * sinT[(size_t)p*DR + d];
    }
}

// ---------------- copy past cache rows into output cache ----------------
__global__ void copy_cache_kernel(const float4* __restrict__ past, float* __restrict__ out_cache)
{
    int t = blockIdx.x, b = blockIdx.y, i = threadIdx.x;   // 144 threads
    float4* dst = (float4*)(out_cache + ((size_t)b*TT + t) * QFD);
    dst[i] = past[((size_t)b*(TT-1) + t) * (QFD/4) + i];
}

// ---------------- absorption: q_lat[b,h,:] = q_nope[b,h,:] @ W_k[h]; pack q_full ----------------
__global__ void absorb_kernel(const float* __restrict__ w_kvb)
{
    int h = blockIdx.x, c = threadIdx.x;   // 512 threads
    __shared__ float qs[4][DN];
    int b0 = c >> 7, d0 = c & 127;
    qs[b0][d0] = g_q[(size_t)b0*QROWS + h*DQK + d0];
    __syncthreads();
    float acc[4] = {0.f, 0.f, 0.f, 0.f};
    const float* wk = w_kvb + (size_t)h*256*KVL + c;
    #pragma unroll 4
    for (int d = 0; d < DN; d++) {
        float wv = wk[(size_t)d*KVL];
        acc[0] += qs[0][d]*wv; acc[1] += qs[1][d]*wv;
        acc[2] += qs[2][d]*wv; acc[3] += qs[3][d]*wv;
    }
    #pragma unroll
    for (int b = 0; b < 4; b++)
        g_qfull[((size_t)(b*HH + h))*QFD + c] = acc[b] * SCALE_QK;
    if (c < DR) {
        #pragma unroll
        for (int b = 0; b < 4; b++)
            g_qfull[((size_t)(b*HH + h))*QFD + KVL + c] =
                g_q[(size_t)b*QROWS + h*DQK + DN + c] * SCALE_QK;
    }
}

// ---------------- transpose cache -> ct[b][k][t] ----------------
__global__ void transpose_cache_kernel(const float* __restrict__ cache)
{
    __shared__ float tile[32][33];
    int tb = blockIdx.x * 32, kb = blockIdx.y * 32, b = blockIdx.z;
    int tx = threadIdx.x, ty = threadIdx.y;     // (32, 8)
    for (int i = ty; i < 32; i += 8) {
        int t = tb + i, k = kb + tx;
        if (t < TT && k < QFD) tile[i][tx] = cache[((size_t)b*TT + t)*QFD + k];
    }
    __syncthreads();
    for (int i = ty; i < 32; i += 8) {
        int k = kb + i, t = tb + tx;
        if (t < TT && k < QFD) g_ct[((size_t)b*QFD + k)*TT + t] = tile[tx][i];
    }
}

// ---------------- attention split: scores + partial softmax + partial ctx ----------------
// grid (HH/8, NSPLIT, BB), block 256. split s covers t in [256s, TE) where
// TE = 256(s+1) for s<3, 1025 for s==3 (extra element t=1024 handled by warp 0).
__global__ void attn_split_kernel(const float* __restrict__ cache, const float* __restrict__ mask)
{
    __shared__ float qsm[8*QFD];
    __shared__ float sc[8*SCP2];
    int b = blockIdx.z, split = blockIdx.y, h0 = blockIdx.x * 8, tid = threadIdx.x;
    int T0 = split * 256;
    int TE = (split == NSPLIT-1) ? TT : T0 + 256;
    int cnt = TE - T0;

    for (int i = tid; i < 8*QFD; i += 256) {
        int h = i / QFD, k = i % QFD;
        qsm[i] = g_qfull[((size_t)(b*HH + h0 + h))*QFD + k];
    }
    __syncthreads();

    // ---- phase 1: scores for t = T0 + tid ----
    {
        float acc[8];
        #pragma unroll
        for (int h = 0; h < 8; h++) acc[h] = 0.f;
        const float* ctb = g_ct + (size_t)b*QFD*TT + T0 + tid;
        for (int k = 0; k < QFD; k += 4) {
            float c0 = ctb[(size_t)k*TT];
            float c1 = ctb[(size_t)(k+1)*TT];
            float c2 = ctb[(size_t)(k+2)*TT];
            float c3 = ctb[(size_t)(k+3)*TT];
            #pragma unroll
            for (int h = 0; h < 8; h++) {
                acc[h] += qsm[h*QFD+k]*c0 + qsm[h*QFD+k+1]*c1
                        + qsm[h*QFD+k+2]*c2 + qsm[h*QFD+k+3]*c3;
            }
        }
        float mk = mask[(size_t)b*TT + T0 + tid];
        #pragma unroll
        for (int h = 0; h < 8; h++) sc[h*SCP2 + tid] = acc[h] + mk;

        if (split == NSPLIT-1 && tid < 32) {   // t = 1024 by warp 0
            const float* crow = cache + ((size_t)b*TT + (TT-1))*QFD;
            float mk2 = mask[(size_t)b*TT + (TT-1)];
            for (int h = 0; h < 8; h++) {
                float p = 0.f;
                for (int i = tid; i < QFD; i += 32) p += qsm[h*QFD + i]*crow[i];
                #pragma unroll
                for (int off = 16; off; off >>= 1) p += __shfl_xor_sync(0xffffffffu, p, off);
                if (tid == 0) sc[h*SCP2 + 256] = p + mk2;
            }
        }
    }
    __syncthreads();

    // ---- phase 2: local softmax (warp per head), store m & s ----
    {
        int w = tid >> 5, lane = tid & 31, h = w;
        float m = -1e30f;
        for (int t = lane; t < cnt; t += 32) m = fmaxf(m, sc[h*SCP2 + t]);
        #pragma unroll
        for (int off = 16; off; off >>= 1) m = fmaxf(m, __shfl_xor_sync(0xffffffffu, m, off));
        float s = 0.f;
        for (int t = lane; t < cnt; t += 32) {
            float e = __expf(sc[h*SCP2 + t] - m);
            sc[h*SCP2 + t] = e;
            s += e;
        }
        #pragma unroll
        for (int off = 16; off; off >>= 1) s += __shfl_xor_sync(0xffffffffu, s, off);
        if (lane == 0) {
            int idx = (b*HH + h0 + h)*NSPLIT + split;
            g_pm[idx] = m;
            g_ps[idx] = s;
        }
    }
    __syncthreads();

    // ---- phase 3: partial ctx (unnormalized) ----
    {
        float acc[8][2];
        #pragma unroll
        for (int h = 0; h < 8; h++) { acc[h][0] = 0.f; acc[h][1] = 0.f; }
        const float* cb = cache + (size_t)b*TT*QFD;
        int c0 = tid, c1 = tid + 256;
        for (int t = T0; t < TE; t++) {
            const float* crow = cb + (size_t)t*QFD;
            float v0 = crow[c0], v1 = crow[c1];
            int tl = t - T0;
            #pragma unroll
            for (int h = 0; h < 8; h++) {
                float a = sc[h*SCP2 + tl];
                acc[h][0] += a*v0; acc[h][1] += a*v1;
            }
        }
        #pragma unroll
        for (int h = 0; h < 8; h++) {
            size_t base = ((size_t)(b*HH + h0 + h)*NSPLIT + split)*KVL;
            g_pctx[base + c0] = acc[h][0];
            g_pctx[base + c1] = acc[h][1];
        }
    }
}

// ---------------- flash combine over splits ----------------
__global__ void attn_combine_kernel()
{
    int h = blockIdx.x, b = blockIdx.y, tid = threadIdx.x;
    int idx = b*HH + h;
    float m = -1e30f;
    #pragma unroll
    for (int s = 0; s < NSPLIT; s++) m = fmaxf(m, g_pm[idx*NSPLIT + s]);
    float e[NSPLIT]; float ssum = 0.f;
    #pragma unroll
    for (int s = 0; s < NSPLIT; s++) {
        e[s] = __expf(g_pm[idx*NSPLIT + s] - m);
        ssum += g_ps[idx*NSPLIT + s] * e[s];
    }
    float inv = 1.0f / ssum;
    for (int c = tid; c < KVL; c += 256) {
        float acc = 0.f;
        #pragma unroll
        for (int s = 0; s < NSPLIT; s++)
            acc += g_pctx[((size_t)idx*NSPLIT + s)*KVL + c] * e[s];
        g_ctxlat[(size_t)idx*KVL + c] = acc * inv;
    }
}

// ---------------- V projection ----------------
__global__ void vproj_kernel(const float* __restrict__ w_kvb)
{
    int h = blockIdx.x, tid = threadIdx.x, w = tid >> 5, lane = tid & 31;
    for (int dv = w; dv < DV; dv += 8) {
        const float* wr = w_kvb + ((size_t)(h*256 + DN + dv))*KVL;
        float p0 = 0.f, p1 = 0.f, p2 = 0.f, p3 = 0.f;
        #pragma unroll 4
        for (int i = lane; i < KVL; i += 32) {
            float wv = wr[i];
            p0 += wv * g_ctxlat[((size_t)(0*HH + h))*KVL + i];
            p1 += wv * g_ctxlat[((size_t)(1*HH + h))*KVL + i];
            p2 += wv * g_ctxlat[((size_t)(2*HH + h))*KVL + i];
            p3 += wv * g_ctxlat[((size_t)(3*HH + h))*KVL + i];
        }
        #pragma unroll
        for (int off = 16; off; off >>= 1) {
            p0 += __shfl_xor_sync(0xffffffffu, p0, off);
            p1 += __shfl_xor_sync(0xffffffffu, p1, off);
            p2 += __shfl_xor_sync(0xffffffffu, p2, off);
            p3 += __shfl_xor_sync(0xffffffffu, p3, off);
        }
        if (lane == 0) {
            g_ctx[(size_t)0*CTXD + h*DV + dv] = p0;
            g_ctx[(size_t)1*CTXD + h*DV + dv] = p1;
            g_ctx[(size_t)2*CTXD + h*DV + dv] = p2;
            g_ctx[(size_t)3*CTXD + h*DV + dv] = p3;
        }
    }
}

// ---------------- host launch ----------------
extern "C" void kernel_launch(void* const* d_in, const int* in_sizes, int n_in,
                              void* d_out, int out_size)
{
    const float* x      = (const float*)d_in[0];
    const float* mask   = (const float*)d_in[1];
    const int*   posw   = (const int*)  d_in[2];
    const float* past   = (const float*)d_in[3];
    const float* cosT   = (const float*)d_in[4];
    const float* sinT   = (const float*)d_in[5];
    const float* w_qa   = (const float*)d_in[6];
    const float* gq     = (const float*)d_in[7];
    const float* w_qb   = (const float*)d_in[8];
    const float* w_kva  = (const float*)d_in[9];
    const float* gkv    = (const float*)d_in[10];
    const float* w_kvb  = (const float*)d_in[11];
    const float* w_o    = (const float*)d_in[12];

    float* out_attn  = (float*)d_out;                  // [4,1,7168]
    float* out_cache = out_attn + (size_t)BB*HID;      // [4,1025,576]

    float *p_qa, *p_qan, *p_q, *p_ckv, *p_ctx;
    cudaGetSymbolAddress((void**)&p_qa,  g_qa);
    cudaGetSymbolAddress((void**)&p_qan, g_qan);
    cudaGetSymbolAddress((void**)&p_q,   g_q);
    cudaGetSymbolAddress((void**)&p_ckv, g_ckv);
    cudaGetSymbolAddress((void**)&p_ctx, g_ctx);

    // q_a = x @ w_qa.T         (44 MB weight stream)
    gemv_smem_kernel<8><<<QL/8, 256>>>((const float4*)w_qa, (const float4*)x, p_qa, HID/4, QL);
    // ckv = x @ w_kva.T        (16.5 MB)
    gemv_smem_kernel<8><<<QFD/8, 256>>>((const float4*)w_kva, (const float4*)x, p_ckv, HID/4, QFD);
    // rmsnorm(q_a)
    rmsnorm_q_kernel<<<BB, 256>>>(gq);
    // q = q_an @ w_qb.T        (151 MB)
    gemv_smem_kernel<16><<<QROWS/16, 512>>>((const float4*)w_qb, (const float4*)p_qan, p_q, QL/4, QROWS);
    // rmsnorm c_kv + RoPE k_pe -> cache row t=1024
    ckv_post_kernel<<<BB, 256>>>(gkv, cosT, sinT, posw, out_cache);
    // past rows -> output cache
    copy_cache_kernel<<<dim3(TT-1, BB), QFD/4>>>((const float4*)past, out_cache);
    // RoPE q_pe
    rope_q_kernel<<<dim3(HH, BB), DR>>>(cosT, sinT, posw);
    // absorption + q packing
    absorb_kernel<<<HH, 512>>>(w_kvb);
    // transpose cache
    transpose_cache_kernel<<<dim3((TT+31)/32, (QFD+31)/32, BB), dim3(32, 8)>>>(out_cache);
    // attention: split-KV
    attn_split_kernel<<<dim3(HH/8, NSPLIT, BB), 256>>>(out_cache, mask);
    attn_combine_kernel<<<dim3(HH, BB), 256>>>();
    // ctx = ctx_lat @ W_v      (33 MB)
    vproj_kernel<<<HH, 256>>>(w_kvb);
    // attn_out = ctx @ w_o.T   (470 MB)
    gemv_smem_kernel<16><<<HID/16, 512>>>((const float4*)w_o, (const float4*)p_ctx, out_attn, CTXD/4, HID);
}